// round 13
// baseline (speedup 1.0000x reference)
#include <cuda_runtime.h>
#include <math.h>

#define TN     512
#define TRANGE 8.0f                              // table covers x0 in [-8, 8)
#define TSCALE ((float)TN / (2.0f * TRANGE))     // 32
#define TOFFS  ((float)(TN / 2))                 // 256

#define TPB    384                               // threads per CTA (= elements)
#define ROWSB  (TPB / 6)                         // 64 output rows per CTA

// Constant gate weights (prescaled): [0:4) w_ih' [4:8) w_hh' [8:12) bias'
// (i,f,o gates scaled by 0.5 to fold into sigmoid; g unscaled)
// [12:30) w_lin  [30] b_lin   (lin part also mirrored in smem ws[])
__constant__ float c_w[31];

__device__ float  g_stage[31];
__device__ float4 g_tab[TN];   // (h0, c0, dh, dc) as function of x0

__device__ __forceinline__ float tanh_fast(float x) {
    float y;
    asm("tanh.approx.f32 %0, %1;" : "=f"(y) : "f"(x));
    return y;
}
// argument already prescaled by 0.5
__device__ __forceinline__ float sigmoid_pre(float half_x) {
    return fmaf(tanh_fast(half_x), 0.5f, 0.5f);
}

// ---------------- setup: stage weights + build exact step0 table -----------
__device__ __forceinline__ void step0_exact(
    float x, float wi, float wg, float wo, float bi, float bg, float bo,
    float* h0, float* c0)
{
    float i0 = 1.0f / (1.0f + expf(-(fmaf(wi, x, bi))));
    float g0 = tanhf(fmaf(wg, x, bg));
    float o0 = 1.0f / (1.0f + expf(-(fmaf(wo, x, bo))));
    float c  = i0 * g0;
    *c0 = c;
    *h0 = o0 * tanhf(c);
}

__global__ void setup_kernel(const float* __restrict__ w_ih,
                             const float* __restrict__ w_hh,
                             const float* __restrict__ b_ih,
                             const float* __restrict__ b_hh,
                             const float* __restrict__ w_lin,
                             const float* __restrict__ b_lin)
{
    int t = threadIdx.x;
    if (t < 4) {
        float s = (t == 2) ? 1.0f : 0.5f;       // g gate unscaled
        g_stage[t]     = w_ih[t] * s;
        g_stage[4 + t] = w_hh[t] * s;
        g_stage[8 + t] = (b_ih[t] + b_hh[t]) * s;
    } else if (t < 22) {
        g_stage[8 + t] = w_lin[t - 4];          // 12..29
    } else if (t == 22) {
        g_stage[30] = b_lin[0];
    }

    const float wi = w_ih[0], wg = w_ih[2], wo = w_ih[3];
    const float bi = b_ih[0] + b_hh[0];
    const float bg = b_ih[2] + b_hh[2];
    const float bo = b_ih[3] + b_hh[3];
    const float inv = 1.0f / TSCALE;

    for (int i = t; i < TN; i += blockDim.x) {
        float x0 = ((float)i       - TOFFS) * inv;
        float x1 = ((float)(i + 1) - TOFFS) * inv;
        float h0, c0, h1, c1;
        step0_exact(x0, wi, wg, wo, bi, bg, bo, &h0, &c0);
        step0_exact(x1, wi, wg, wo, bi, bg, bo, &h1, &c1);
        g_tab[i] = make_float4(h0, c0, h1 - h0, c1 - c0);
    }
}

// step-0 table gather: (h0, c0) as float2, from x0 only
__device__ __forceinline__ float2 step0_gather(float x0, const float4* __restrict__ stab) {
    float t = fmaf(x0, TSCALE, TOFFS);
    t = fminf(fmaxf(t, 0.0f), (float)TN - 0.51f);
    int   i  = (int)t;
    float dx = t - (float)i;
    float4 e = stab[i];
    return make_float2(fmaf(dx, e.z, e.x), fmaf(dx, e.w, e.y));
}

// ---------------- main kernel: one LSTM element per thread -----------------
__global__ __launch_bounds__(TPB) void lstm_lin_kernel(
    const float* __restrict__ x, float* __restrict__ out)
{
    __shared__ float4 stab[TN];      // 8 KB step-0 table
    __shared__ float  ws[19];        // w_lin[18] + b_lin
    __shared__ float  partial[TPB];  // per-element partial dot products

    const int tid = threadIdx.x;

    // fill table + lin weights
    for (int i = tid; i < TN; i += TPB)
        stab[i] = __ldg(&g_tab[i]);
    if (tid < 19)
        ws[tid] = __ldg(&g_stage[12 + tid]);   // 12..29 = w_lin, 30 = b_lin
    __syncthreads();

    // this thread's element: 3 consecutive input floats
    const size_t T = (size_t)blockIdx.x * TPB + tid;
    const float* px = x + 3 * T;
    const float x0 = __ldg(px + 0);
    const float x1 = __ldg(px + 1);
    const float x2 = __ldg(px + 2);

    // step 0 via table (index depends only on x0)
    float2 hc = step0_gather(x0, stab);
    float h = hc.x, c = hc.y;
    const int m3 = (tid % 6) * 3;    // w_lin base for this element
    float p = h * ws[m3];

    // step 1 (MUFU gates)
    {
        float i1 = sigmoid_pre(fmaf(c_w[4], h, fmaf(c_w[0], x1, c_w[8])));
        float f1 = sigmoid_pre(fmaf(c_w[5], h, fmaf(c_w[1], x1, c_w[9])));
        float g1 = tanh_fast  (fmaf(c_w[6], h, fmaf(c_w[2], x1, c_w[10])));
        float o1 = sigmoid_pre(fmaf(c_w[7], h, fmaf(c_w[3], x1, c_w[11])));
        c = fmaf(f1, c, i1 * g1);
        h = o1 * tanh_fast(c);
        p = fmaf(h, ws[m3 + 1], p);
    }
    // step 2
    {
        float i2 = sigmoid_pre(fmaf(c_w[4], h, fmaf(c_w[0], x2, c_w[8])));
        float f2 = sigmoid_pre(fmaf(c_w[5], h, fmaf(c_w[1], x2, c_w[9])));
        float g2 = tanh_fast  (fmaf(c_w[6], h, fmaf(c_w[2], x2, c_w[10])));
        float o2 = sigmoid_pre(fmaf(c_w[7], h, fmaf(c_w[3], x2, c_w[11])));
        c = fmaf(f2, c, i2 * g2);
        h = o2 * tanh_fast(c);
        p = fmaf(h, ws[m3 + 2], p);
    }

    partial[tid] = p;
    __syncthreads();

    // 6-element reduction: threads 0..63 each produce one output row
    if (tid < ROWSB) {
        const float* pp = partial + 6 * tid;
        float s = ws[18] + pp[0] + pp[1] + pp[2] + pp[3] + pp[4] + pp[5];
        out[(size_t)blockIdx.x * ROWSB + tid] = s;
    }
}

extern "C" void kernel_launch(void* const* d_in, const int* in_sizes, int n_in,
                              void* d_out, int out_size)
{
    // Inputs: x, w_ih, w_hh, b_ih, b_hh, w_lin, b_lin
    const float* x = (const float*)d_in[0];

    setup_kernel<<<1, 256>>>((const float*)d_in[1], (const float*)d_in[2],
                             (const float*)d_in[3], (const float*)d_in[4],
                             (const float*)d_in[5], (const float*)d_in[6]);

    void* stage_ptr = nullptr;
    cudaGetSymbolAddress(&stage_ptr, g_stage);
    cudaMemcpyToSymbolAsync(c_w, stage_ptr, 31 * sizeof(float), 0,
                            cudaMemcpyDeviceToDevice, 0);

    int nblocks = out_size / ROWSB;   // 32768 CTAs, 64 rows each
    lstm_lin_kernel<<<nblocks, TPB>>>(x, (float*)d_out);
}

// round 14
// speedup vs baseline: 1.6212x; 1.6212x over previous
#include <cuda_runtime.h>
#include <math.h>

#define TN     512
#define TRANGE 8.0f                              // table covers x0 in [-8, 8)
#define TSCALE ((float)TN / (2.0f * TRANGE))     // 32
#define TOFFS  ((float)(TN / 2))                 // 256
#define TINV   (1.0f / TSCALE)                   // u-step per index

#define RPC    256                               // rows per chunk (= blockDim)
#define F4PC   (RPC * 18 / 4)                    // float4 per chunk = 1152

#define MAGIC  8388608.0f                        // 2^23: RN round-to-int trick

// Constant weights (prescaled): [0:4) w_ih' [4:8) w_hh' [8:12) bias'
// (i,f,o gates scaled by 0.5 to fold into sigmoid; g unscaled)
// [12:30) w_lin  [30] b_lin
__constant__ float c_w[31];

__device__ float  g_stage[31];
__device__ float4 g_tab[TN];   // (h0, c0, dh, dc): centered-interp step0 table

__device__ __forceinline__ float tanh_fast(float x) {
    float y;
    asm("tanh.approx.f32 %0, %1;" : "=f"(y) : "f"(x));
    return y;
}
// argument already prescaled by 0.5
__device__ __forceinline__ float sigmoid_pre(float half_x) {
    return fmaf(tanh_fast(half_x), 0.5f, 0.5f);
}

// ---------------- setup: stage weights + build exact step0 table -----------
__device__ __forceinline__ void step0_exact(
    float x, float wi, float wg, float wo, float bi, float bg, float bo,
    float* h0, float* c0)
{
    float i0 = 1.0f / (1.0f + expf(-(fmaf(wi, x, bi))));
    float g0 = tanhf(fmaf(wg, x, bg));
    float o0 = 1.0f / (1.0f + expf(-(fmaf(wo, x, bo))));
    float c  = i0 * g0;
    *c0 = c;
    *h0 = o0 * tanhf(c);
}

__global__ void setup_kernel(const float* __restrict__ w_ih,
                             const float* __restrict__ w_hh,
                             const float* __restrict__ b_ih,
                             const float* __restrict__ b_hh,
                             const float* __restrict__ w_lin,
                             const float* __restrict__ b_lin)
{
    int t = threadIdx.x;
    if (t < 4) {
        float s = (t == 2) ? 1.0f : 0.5f;       // g gate unscaled
        g_stage[t]     = w_ih[t] * s;
        g_stage[4 + t] = w_hh[t] * s;
        g_stage[8 + t] = (b_ih[t] + b_hh[t]) * s;
    } else if (t < 22) {
        g_stage[8 + t] = w_lin[t - 4];          // 12..29
    } else if (t == 22) {
        g_stage[30] = b_lin[0];
    }

    const float wi = w_ih[0], wg = w_ih[2], wo = w_ih[3];
    const float bi = b_ih[0] + b_hh[0];
    const float bg = b_ih[2] + b_hh[2];
    const float bo = b_ih[3] + b_hh[3];

    for (int i = t; i < TN; i += blockDim.x) {
        float u = ((float)i - TOFFS) * TINV;
        float h0, c0, hp, cp, hm, cm;
        step0_exact(u,                wi, wg, wo, bi, bg, bo, &h0, &c0);
        step0_exact(u + 0.5f * TINV,  wi, wg, wo, bi, bg, bo, &hp, &cp);
        step0_exact(u - 0.5f * TINV,  wi, wg, wo, bi, bg, bo, &hm, &cm);
        // centered interp: F(i+dx) ~ F_i + dx*(F(u+D/2)-F(u-D/2)), dx in [-.5,.5]
        g_tab[i] = make_float4(h0, c0, hp - hm, cp - cm);
    }
}

// Steps 1-2 of one element given (h,c) from the step-0 gather.
#define STEPS12(ACC, H, C, X1, X2, WI)                                        \
    do {                                                                      \
        float h_ = (H), c_ = (C);                                             \
        ACC = fmaf(h_, c_w[(WI)], ACC);                                       \
        float i1_ = sigmoid_pre(fmaf(c_w[4], h_, fmaf(c_w[0], (X1), c_w[8])));\
        float f1_ = sigmoid_pre(fmaf(c_w[5], h_, fmaf(c_w[1], (X1), c_w[9])));\
        float g1_ = tanh_fast  (fmaf(c_w[6], h_, fmaf(c_w[2], (X1), c_w[10])));\
        float o1_ = sigmoid_pre(fmaf(c_w[7], h_, fmaf(c_w[3], (X1), c_w[11])));\
        c_ = fmaf(f1_, c_, i1_ * g1_);                                        \
        h_ = o1_ * tanh_fast(c_);                                             \
        ACC = fmaf(h_, c_w[(WI) + 1], ACC);                                   \
        float i2_ = sigmoid_pre(fmaf(c_w[4], h_, fmaf(c_w[0], (X2), c_w[8])));\
        float f2_ = sigmoid_pre(fmaf(c_w[5], h_, fmaf(c_w[1], (X2), c_w[9])));\
        float g2_ = tanh_fast  (fmaf(c_w[6], h_, fmaf(c_w[2], (X2), c_w[10])));\
        float o2_ = sigmoid_pre(fmaf(c_w[7], h_, fmaf(c_w[3], (X2), c_w[11])));\
        c_ = fmaf(f2_, c_, i2_ * g2_);                                        \
        h_ = o2_ * tanh_fast(c_);                                             \
        ACC = fmaf(h_, c_w[(WI) + 2], ACC);                                   \
    } while (0)

// step-0 gather with NO float<->int conversion instructions (no XU-pipe use):
// round via 2^23 magic add (FADD), index via mantissa bits (LOP), dx via FADDs.
#define STEP0_GATHER(X0, H, C)                                                \
    do {                                                                      \
        float t_ = fmaf((X0), TSCALE, TOFFS);                                 \
        t_ = fminf(fmaxf(t_, 0.0f), (float)(TN - 1));                         \
        float y_  = t_ + MAGIC;              /* RN -> nearest int */          \
        int   i_  = __float_as_int(y_) & 0xFFFF;                              \
        float dx_ = t_ - (y_ - MAGIC);       /* in [-0.5, 0.5] */             \
        float4 e_ = stab[i_];                                                 \
        H = fmaf(dx_, e_.z, e_.x);                                            \
        C = fmaf(dx_, e_.w, e_.y);                                            \
    } while (0)

// ---------------- main kernel: one 256-row chunk per CTA -------------------
__global__ __launch_bounds__(256) void lstm_lin_kernel(
    const float* __restrict__ x, float* __restrict__ out)
{
    __shared__ float4 stab[TN];          // 8 KB step-0 table
    __shared__ float  xs[RPC * 18];      // 18 KB input chunk, linear layout

    const int tid = threadIdx.x;

    // table fill (coalesced, L2-hot)
    stab[tid]       = __ldg(&g_tab[tid]);
    stab[tid + 256] = __ldg(&g_tab[tid + 256]);

    // chunk load: fully coalesced float4, linear conflict-free STS.128
    {
        const float4* src = reinterpret_cast<const float4*>(x)
                          + (size_t)blockIdx.x * F4PC;
        float4* xs4 = reinterpret_cast<float4*>(xs);
#pragma unroll
        for (int k = 0; k < 4; k++)
            xs4[tid + 256 * k] = __ldg(src + tid + 256 * k);
        if (tid < F4PC - 1024)
            xs4[tid + 1024] = __ldg(src + tid + 1024);
    }
    __syncthreads();

    // compute: thread tid owns row tid of the chunk (18 floats, smem-resident)
    const float* row = xs + tid * 18;

    float acc = c_w[30];
    float h, c;
    STEP0_GATHER(row[ 0], h, c); STEPS12(acc, h, c, row[ 1], row[ 2], 12);
    STEP0_GATHER(row[ 3], h, c); STEPS12(acc, h, c, row[ 4], row[ 5], 15);
    STEP0_GATHER(row[ 6], h, c); STEPS12(acc, h, c, row[ 7], row[ 8], 18);
    STEP0_GATHER(row[ 9], h, c); STEPS12(acc, h, c, row[10], row[11], 21);
    STEP0_GATHER(row[12], h, c); STEPS12(acc, h, c, row[13], row[14], 24);
    STEP0_GATHER(row[15], h, c); STEPS12(acc, h, c, row[16], row[17], 27);

    out[blockIdx.x * RPC + tid] = acc;
}

extern "C" void kernel_launch(void* const* d_in, const int* in_sizes, int n_in,
                              void* d_out, int out_size)
{
    // Inputs: x, w_ih, w_hh, b_ih, b_hh, w_lin, b_lin
    const float* x = (const float*)d_in[0];

    setup_kernel<<<1, 256>>>((const float*)d_in[1], (const float*)d_in[2],
                             (const float*)d_in[3], (const float*)d_in[4],
                             (const float*)d_in[5], (const float*)d_in[6]);

    void* stage_ptr = nullptr;
    cudaGetSymbolAddress(&stage_ptr, g_stage);
    cudaMemcpyToSymbolAsync(c_w, stage_ptr, 31 * sizeof(float), 0,
                            cudaMemcpyDeviceToDevice, 0);

    int nchunks = out_size / RPC;   // 8192 CTAs, one chunk each
    lstm_lin_kernel<<<nchunks, 256>>>(x, (float*)d_out);
}